// round 14
// baseline (speedup 1.0000x reference)
#include <cuda_runtime.h>
#include <cuda_fp16.h>
#include <cstdint>

// ============================================================================
// CATSCluster fused kernel — sm_103 baseline-PTX tensor path.
// Round-14: r13 with the chunk-stride bug FIXED (one L1 weight chunk =
// 2048 uint4, not 128 — r13's ring refilled garbage from chunk 0).
// Design: r11 base (64-row block, 256 thr, 2 CTAs/SM, L1 warp 64m x 32n,
// L2 warp 32m x 32n, register-X prefetch, one barrier/chunk) +
// PAIRED B FRAGMENTS: weights packed [n8][lane][j][8B] so one LDG.128
// fetches the (j, j+1) fragment pair -> B LDG count halved in both GEMMs.
//
//   X = X_data[:, 1:, :]  (16 x 4096 x 2304 fp32)
//   p1 = X[.., 768:1536] -> relu(relu(p1@W1^T)@W2^T) = Ha2   (128)
//   p2 = X[..,1536:2304] -> same weights             = Hb2
//   q  = X[..,   0: 768] -> relu(relu(q @W3^T)@W4^T) = Hq2
//   out = tanh(relu( (Hq2 * |Ha2-Hb2|) @ W5^T ))
// ============================================================================

// ---- smem layout (bytes), 64-row block ----
static constexpr int AF16_STRIDE = 144;                   // 64 f16 + 16B pad
static constexpr int AF16_BYTES  = 64 * AF16_STRIDE;      // 9216
static constexpr int SM_W5   = 0;                         // 512 B
static constexpr int SM_PART = 512;                       // float[64][4] = 1024
static constexpr int SM_AF16 = 2560;                      // 2 x 9216 (double buffer)
static constexpr int SM_H1   = SM_AF16 + 2 * AF16_BYTES;  // 64 x 528 = 33792
static constexpr int SM_D    = SM_H1 + 64 * 528;          // 64 x 272 = 17408
static constexpr int SMEM_BYTES = SM_D + 64 * 272;        // 74368 -> 2 CTAs/SM

// L1 weight chunk size in uint4: 32 n8 * 32 lanes * 4 j * 4 halves / 8 = 2048
static constexpr int B1_CHUNK_U4 = 2048;

// Fragment-packed fp16 weights, PAIRED layout (prep kernel fills every launch).
// L1: [chunk 12][n8-tile 32][lane 32][j 4][4 halves]   (j adjacent per lane)
// L2: [n8-tile 16][lane 32][j 16][4 halves]
__device__ __half g_B1[2][12 * 32 * 32 * 4 * 4];   // W1, W3
__device__ __half g_B2[2][16 * 32 * 16 * 4];       // W2, W4

// ---------------------------------------------------------------- helpers
__device__ __forceinline__ uint32_t smem_u32(const void* p) {
    return (uint32_t)__cvta_generic_to_shared(p);
}
__device__ __forceinline__ void ldm_x4(uint32_t r[4], uint32_t addr) {
    asm volatile("ldmatrix.sync.aligned.m8n8.x4.shared.b16 {%0,%1,%2,%3}, [%4];"
                 : "=r"(r[0]), "=r"(r[1]), "=r"(r[2]), "=r"(r[3]) : "r"(addr));
}
__device__ __forceinline__ void mma16816(float c[4], const uint32_t a[4],
                                         uint32_t b0, uint32_t b1) {
    asm volatile(
        "mma.sync.aligned.m16n8k16.row.col.f32.f16.f16.f32 "
        "{%0,%1,%2,%3}, {%4,%5,%6,%7}, {%8,%9}, {%0,%1,%2,%3};"
        : "+f"(c[0]), "+f"(c[1]), "+f"(c[2]), "+f"(c[3])
        : "r"(a[0]), "r"(a[1]), "r"(a[2]), "r"(a[3]), "r"(b0), "r"(b1));
}
__device__ __forceinline__ uint32_t h2u(__half2 h) {
    return *reinterpret_cast<uint32_t*>(&h);
}

// ------------------------------------------------- weight frag-pack kernel
__global__ void prep_kernel(const float* __restrict__ W1, const float* __restrict__ W2,
                            const float* __restrict__ W3, const float* __restrict__ W4) {
    int e = blockIdx.x * blockDim.x + threadIdx.x;    // 0 .. 196607
    {
        // L1 weights: W[n(256)][k(768)] -> [kc][n8][lane][j][p*2+h]
        int n = e / 768, k = e % 768;
        int kc = k >> 6;
        int j  = (k >> 4) & 3;
        int kl = k & 15;
        int p  = kl >> 3;
        int pos = kl & 7;
        int lane = (n & 7) * 4 + (pos >> 1);
        int h = pos & 1;
        int idx = ((((kc * 32 + (n >> 3)) * 32 + lane) * 4 + j) << 2) + p * 2 + h;
        g_B1[0][idx] = __float2half_rn(W1[e]);
        g_B1[1][idx] = __float2half_rn(W3[e]);
    }
    if (e < 128 * 256) {
        // L2 weights: W[n(128)][k(256)] -> [n8][lane][j][p*2+h]
        int n = e / 256, k = e % 256;
        int j  = k >> 4;
        int kl = k & 15;
        int p  = kl >> 3;
        int pos = kl & 7;
        int lane = (n & 7) * 4 + (pos >> 1);
        int h = pos & 1;
        int idx = ((((n >> 3) * 32 + lane) * 16 + j) << 2) + p * 2 + h;
        g_B2[0][idx] = __float2half_rn(W2[e]);
        g_B2[1][idx] = __float2half_rn(W4[e]);
    }
}

// ----------------------------------------------------------------- main kernel
__global__ void __launch_bounds__(256, 2) fused_kernel(
    const float* __restrict__ X, const float* __restrict__ W5, float* __restrict__ out) {
    extern __shared__ __align__(128) char smem[];
    const uint32_t sb = smem_u32(smem);
    const int tid = threadIdx.x;
    const int w   = tid >> 5;           // warp 0..7
    const int l   = tid & 31;
    const int lq  = l & 3;

    const long long blk = blockIdx.x;                  // 1024 blocks, 64 rows each
    const float* Xbase = X + ((blk >> 6) * 4097LL + (blk & 63) * 64LL + 1LL) * 2304LL;

    // X prefetch assignment: 4 threads/row, 16 floats (64B) each
    const int xrow = tid >> 2, xseg = tid & 3;
    const float* xsrc_row = Xbase + (long long)xrow * 2304 + xseg * 16;

    // chunk c (0..35): slice s=c/12, k-chunk kc=c%12, AF16 buffer c&1.
    float4 xv0, xv1, xv2, xv3;
    auto ldg_chunk = [&](int c) {
        int ss = c / 12, kk = c % 12;
        int soff = (ss == 0) ? 768 : (ss == 1) ? 1536 : 0;   // p1, p2, q
        const float4* src = (const float4*)(xsrc_row + soff + kk * 64);
        xv0 = src[0]; xv1 = src[1]; xv2 = src[2]; xv3 = src[3];
    };
    // this thread's STS target within an AF16 buffer (32B fp16 for its 16 floats)
    const uint32_t xdst = sb + SM_AF16 + xrow * AF16_STRIDE + xseg * 32;

    ldg_chunk(0);
    if (tid < 128) ((float*)(smem + SM_W5))[tid] = W5[tid];

    const float* W5s = (const float*)(smem + SM_W5);
    float* parts = (float*)(smem + SM_PART);

    // layer-2 warp grid: 2m x 4n
    const int wm2 = w >> 2;             // m-half (32 rows)
    const int wq2 = w & 3;              // n-quarter (32 cols)

    // ldmatrix lane addressing
    const uint32_t aF16lane = sb + SM_AF16 + (l & 15) * AF16_STRIDE + (l >> 4) * 16;
    const uint32_t h1lane   = sb + SM_H1 + (wm2 * 32 + (l & 15)) * 528 + (l >> 4) * 16;

    // uint4 B bases (paired layout):
    //  L1: per n8-tile 64 uint4; warp w covers n8-tiles w*4..w*4+3; lane stride 2
    //  L2: per n8-tile 256 uint4; warp wq2 covers n8 wq2*4..+3; lane stride 8
    // distance-2 paired ring, preloaded for slice 0 chunk 0 (jp0, jp1)
    uint4 bq[2][4];
    {
        const uint4* bp = (const uint4*)g_B1[0] + w * 256 + l * 2;
        #pragma unroll
        for (int t = 0; t < 4; t++) {
            bq[0][t] = bp[t * 64 + 0];      // j0,j1
            bq[1][t] = bp[t * 64 + 1];      // j2,j3
        }
    }

    int c = 0;
    for (int s = 0; s < 3; s++) {
        const uint4* B1g = (const uint4*)g_B1[s == 2 ? 1 : 0] + w * 256 + l * 2;
        const uint4* B2g = (const uint4*)g_B2[s == 2 ? 1 : 0] + wq2 * 1024 + l * 8;

        // ================= layer 1: acc[4 mf][4 t][4] = Xslice @ W^T ============
        float acc[4][4][4];
        #pragma unroll
        for (int a = 0; a < 4; a++)
            #pragma unroll
            for (int b = 0; b < 4; b++)
                #pragma unroll
                for (int q = 0; q < 4; q++) acc[a][b][q] = 0.f;

        #pragma unroll 1
        for (int kc = 0; kc < 12; kc++) {
            // ---- convert register X -> fp16 AF16[c&1] (32B STS) ----
            {
                uint32_t dst = xdst + (c & 1) * AF16_BYTES;
                uint32_t p0 = h2u(__floats2half2_rn(xv0.x, xv0.y));
                uint32_t p1 = h2u(__floats2half2_rn(xv0.z, xv0.w));
                uint32_t p2 = h2u(__floats2half2_rn(xv1.x, xv1.y));
                uint32_t p3 = h2u(__floats2half2_rn(xv1.z, xv1.w));
                asm volatile("st.shared.v4.b32 [%0], {%1,%2,%3,%4};"
                             :: "r"(dst), "r"(p0), "r"(p1), "r"(p2), "r"(p3));
                uint32_t p4 = h2u(__floats2half2_rn(xv2.x, xv2.y));
                uint32_t p5 = h2u(__floats2half2_rn(xv2.z, xv2.w));
                uint32_t p6 = h2u(__floats2half2_rn(xv3.x, xv3.y));
                uint32_t p7 = h2u(__floats2half2_rn(xv3.z, xv3.w));
                asm volatile("st.shared.v4.b32 [%0], {%1,%2,%3,%4};"
                             :: "r"(dst + 16), "r"(p4), "r"(p5), "r"(p6), "r"(p7));
            }
            // LDG for chunk c+1 issued BEFORE the barrier (WAR-safe: STS above
            // consumed xv); global latency overlaps barrier + this chunk's MMAs.
            if (c + 1 < 36) ldg_chunk(c + 1);
            __syncthreads();                 // AF16[c&1] complete (barrier c-1 ordered
                                             // all MMA readers of this buffer)

            const uint32_t aB = aF16lane + (c & 1) * AF16_BYTES;
            // next chunk's B base: one chunk = B1_CHUNK_U4 (2048) uint4   [r13 bug fix]
            const uint4* bGn = B1g + ((c % 12) + 1) * B1_CHUNK_U4;

            #pragma unroll
            for (int j = 0; j < 4; j++) {
                uint32_t afr[4][4];
                #pragma unroll
                for (int mf = 0; mf < 4; mf++)
                    ldm_x4(afr[mf], aB + mf * 16 * AF16_STRIDE + j * 32);
                const int jp = j >> 1;
                #pragma unroll
                for (int t = 0; t < 4; t++) {
                    uint32_t b0 = (j & 1) ? bq[jp][t].z : bq[jp][t].x;
                    uint32_t b1 = (j & 1) ? bq[jp][t].w : bq[jp][t].y;
                    // after the odd half is consumed, refill this jp slot with
                    // the NEXT chunk's pair (distance >= 2 j-steps)
                    if ((j & 1) && kc < 11) bq[jp][t] = bGn[t * 64 + jp];
                    mma16816(acc[0][t], afr[0], b0, b1);
                    mma16816(acc[1][t], afr[1], b0, b1);
                    mma16816(acc[2][t], afr[2], b0, b1);
                    mma16816(acc[3][t], afr[3], b0, b1);
                }
            }
            c++;
        }

        // preload layer-2 B pairs jp0+jp1 EARLY (their L2 latency overlaps the
        // whole H1 store phase + barrier)
        uint4 bq2[2][4];
        #pragma unroll
        for (int t = 0; t < 4; t++) {
            bq2[0][t] = B2g[t * 256 + 0];    // j0,j1
            bq2[1][t] = B2g[t * 256 + 1];    // j2,j3
        }

        // ================= relu -> fp16 -> H1 smem (stride 528) =================
        #pragma unroll
        for (int mf = 0; mf < 4; mf++) {
            #pragma unroll
            for (int t = 0; t < 4; t++) {
                const int r0 = mf * 16 + (l >> 2);
                const int col = w * 32 + t * 8 + lq * 2;
                float* cc = acc[mf][t];
                *(uint32_t*)(smem + SM_H1 + r0 * 528 + col * 2) =
                    h2u(__floats2half2_rn(fmaxf(cc[0], 0.f), fmaxf(cc[1], 0.f)));
                *(uint32_t*)(smem + SM_H1 + (r0 + 8) * 528 + col * 2) =
                    h2u(__floats2half2_rn(fmaxf(cc[2], 0.f), fmaxf(cc[3], 0.f)));
            }
        }
        __syncthreads();

        // ================= layer 2: acc2[2 mf][4 t][4] = H1 @ W2^T ==============
        // warp tile 32m x 32n (grid 2m x 4n)
        float acc2[2][4][4];
        #pragma unroll
        for (int a = 0; a < 2; a++)
            #pragma unroll
            for (int b = 0; b < 4; b++)
                #pragma unroll
                for (int q = 0; q < 4; q++) acc2[a][b][q] = 0.f;

        #pragma unroll
        for (int j = 0; j < 16; j++) {
            uint32_t afr[2][4];
            #pragma unroll
            for (int mf = 0; mf < 2; mf++)
                ldm_x4(afr[mf], h1lane + mf * 16 * 528 + j * 32);
            const int jp = j >> 1, slot = jp & 1;
            #pragma unroll
            for (int t = 0; t < 4; t++) {
                uint32_t b0 = (j & 1) ? bq2[slot][t].z : bq2[slot][t].x;
                uint32_t b1 = (j & 1) ? bq2[slot][t].w : bq2[slot][t].y;
                if ((j & 1) && jp + 2 < 8) bq2[slot][t] = B2g[t * 256 + jp + 2];
                mma16816(acc2[0][t], afr[0], b0, b1);
                mma16816(acc2[1][t], afr[1], b0, b1);
            }
        }

        // preload NEXT slice's layer-1 B ring before the combine phase so its
        // L2 latency hides under the combine ALU work (s==2 has no next slice)
        if (s < 2) {
            const uint4* bn = (const uint4*)g_B1[s == 1 ? 1 : 0] + w * 256 + l * 2;
            #pragma unroll
            for (int t = 0; t < 4; t++) {
                bq[0][t] = bn[t * 64 + 0];
                bq[1][t] = bn[t * 64 + 1];
            }
        }

        // D-buffer cells below: warp (wm2,wq2) owns rows [wm2*32,+32) x cols
        // [wq2*32,+32) in ALL slices -> no cross-warp race; H1 rewritten only
        // after the next slice's chunk barriers.

        // ================= combine via D buffer (stride 272) ====================
        if (s == 0) {
            #pragma unroll
            for (int mf = 0; mf < 2; mf++)
                #pragma unroll
                for (int t = 0; t < 4; t++) {
                    const int r0 = wm2 * 32 + mf * 16 + (l >> 2);
                    const int col = wq2 * 32 + t * 8 + lq * 2;
                    float* cc = acc2[mf][t];
                    *(uint32_t*)(smem + SM_D + r0 * 272 + col * 2) =
                        h2u(__floats2half2_rn(fmaxf(cc[0], 0.f), fmaxf(cc[1], 0.f)));
                    *(uint32_t*)(smem + SM_D + (r0 + 8) * 272 + col * 2) =
                        h2u(__floats2half2_rn(fmaxf(cc[2], 0.f), fmaxf(cc[3], 0.f)));
                }
        } else if (s == 1) {
            #pragma unroll
            for (int mf = 0; mf < 2; mf++)
                #pragma unroll
                for (int t = 0; t < 4; t++) {
                    const int r0 = wm2 * 32 + mf * 16 + (l >> 2);
                    const int col = wq2 * 32 + t * 8 + lq * 2;
                    float* cc = acc2[mf][t];
                    uint32_t* d0 = (uint32_t*)(smem + SM_D + r0 * 272 + col * 2);
                    uint32_t* d1 = (uint32_t*)(smem + SM_D + (r0 + 8) * 272 + col * 2);
                    float2 fa = __half22float2(*(__half2*)d0);
                    float2 fb = __half22float2(*(__half2*)d1);
                    *d0 = h2u(__floats2half2_rn(fabsf(fa.x - fmaxf(cc[0], 0.f)),
                                                fabsf(fa.y - fmaxf(cc[1], 0.f))));
                    *d1 = h2u(__floats2half2_rn(fabsf(fb.x - fmaxf(cc[2], 0.f)),
                                                fabsf(fb.y - fmaxf(cc[3], 0.f))));
                }
        } else {
            // s==2: pd[mf][rr] = per-row partial over this warp's 32 cols
            float pd[2][2] = {{0.f, 0.f}, {0.f, 0.f}};
            #pragma unroll
            for (int mf = 0; mf < 2; mf++)
                #pragma unroll
                for (int t = 0; t < 4; t++) {
                    const int r0 = wm2 * 32 + mf * 16 + (l >> 2);
                    const int col = wq2 * 32 + t * 8 + lq * 2;
                    float* cc = acc2[mf][t];
                    float2 da = __half22float2(*(__half2*)(smem + SM_D + r0 * 272 + col * 2));
                    float2 db = __half22float2(*(__half2*)(smem + SM_D + (r0 + 8) * 272 + col * 2));
                    float w0 = W5s[col], w1 = W5s[col + 1];
                    pd[mf][0] += w0 * fmaxf(cc[0], 0.f) * da.x + w1 * fmaxf(cc[1], 0.f) * da.y;
                    pd[mf][1] += w0 * fmaxf(cc[2], 0.f) * db.x + w1 * fmaxf(cc[3], 0.f) * db.y;
                }
            #pragma unroll
            for (int mf = 0; mf < 2; mf++)
                #pragma unroll
                for (int rr = 0; rr < 2; rr++) {
                    float v = pd[mf][rr];
                    v += __shfl_xor_sync(0xFFFFFFFF, v, 1);
                    v += __shfl_xor_sync(0xFFFFFFFF, v, 2);
                    if (lq == 0) {
                        int row = wm2 * 32 + mf * 16 + rr * 8 + (l >> 2);
                        parts[row * 4 + wq2] = v;    // warp's 32-col partial
                    }
                }
        }
    }

    __syncthreads();
    if (tid < 64) {
        const float* p = parts + tid * 4;
        float sum = (p[0] + p[1]) + (p[2] + p[3]);
        out[blk * 64 + tid] = tanhf(fmaxf(sum, 0.f));
    }
}

// ------------------------------------------------------------------- launcher
extern "C" void kernel_launch(void* const* d_in, const int* in_sizes, int n_in,
                              void* d_out, int out_size) {
    const float* X  = (const float*)d_in[0];
    const float* W1 = (const float*)d_in[1];
    const float* W2 = (const float*)d_in[2];
    const float* W3 = (const float*)d_in[3];
    const float* W4 = (const float*)d_in[4];
    const float* W5 = (const float*)d_in[5];
    (void)in_sizes; (void)n_in; (void)out_size;

    cudaFuncSetAttribute(fused_kernel, cudaFuncAttributeMaxDynamicSharedMemorySize, SMEM_BYTES);

    prep_kernel<<<768, 256>>>(W1, W2, W3, W4);
    fused_kernel<<<1024, 256, SMEM_BYTES>>>(X, W5, (float*)d_out);
}

// round 15
// speedup vs baseline: 1.8004x; 1.8004x over previous
#include <cuda_runtime.h>
#include <cuda_fp16.h>
#include <cstdint>

// ============================================================================
// CATSCluster fused kernel — sm_103 baseline-PTX tensor path.
// Round-15: r11 (285.3us, proven) templated on MF (= rows/16) and launched as
// a MIXED-GRANULARITY grid to kill wave quantization:
//   fused<4>: 888 blocks x 64 rows = 3.00 perfect waves (296 slots = 148SMx2)
//   fused<2>: 272 blocks x 32 rows = the remaining 8704 rows in ~0.55 wave
// (single 1024-block grid = 3.46 waves -> rounds to 4 -> 13.5% idle tail)
//
//   X = X_data[:, 1:, :]  (16 x 4096 x 2304 fp32)
//   p1 = X[.., 768:1536] -> relu(relu(p1@W1^T)@W2^T) = Ha2   (128)
//   p2 = X[..,1536:2304] -> same weights             = Hb2
//   q  = X[..,   0: 768] -> relu(relu(q @W3^T)@W4^T) = Hq2
//   out = tanh(relu( (Hq2 * |Ha2-Hb2|) @ W5^T ))
// ============================================================================

// Fragment-packed fp16 weights (r11 layout: [n8][j][lane], 256B-coalesced).
// L1: [chunk 12][n8-tile 32][k16 4][lane 32][4 halves]
// L2: [n8-tile 16][k16 16][lane 32][4 halves]
__device__ __half g_B1[2][12 * 32 * 4 * 32 * 4];   // W1, W3
__device__ __half g_B2[2][16 * 16 * 32 * 4];       // W2, W4

// ---------------------------------------------------------------- helpers
__device__ __forceinline__ uint32_t smem_u32(const void* p) {
    return (uint32_t)__cvta_generic_to_shared(p);
}
__device__ __forceinline__ void ldm_x4(uint32_t r[4], uint32_t addr) {
    asm volatile("ldmatrix.sync.aligned.m8n8.x4.shared.b16 {%0,%1,%2,%3}, [%4];"
                 : "=r"(r[0]), "=r"(r[1]), "=r"(r[2]), "=r"(r[3]) : "r"(addr));
}
__device__ __forceinline__ void mma16816(float c[4], const uint32_t a[4],
                                         uint32_t b0, uint32_t b1) {
    asm volatile(
        "mma.sync.aligned.m16n8k16.row.col.f32.f16.f16.f32 "
        "{%0,%1,%2,%3}, {%4,%5,%6,%7}, {%8,%9}, {%0,%1,%2,%3};"
        : "+f"(c[0]), "+f"(c[1]), "+f"(c[2]), "+f"(c[3])
        : "r"(a[0]), "r"(a[1]), "r"(a[2]), "r"(a[3]), "r"(b0), "r"(b1));
}
__device__ __forceinline__ uint32_t h2u(__half2 h) {
    return *reinterpret_cast<uint32_t*>(&h);
}

// ------------------------------------------------- weight frag-pack kernel
__global__ void prep_kernel(const float* __restrict__ W1, const float* __restrict__ W2,
                            const float* __restrict__ W3, const float* __restrict__ W4) {
    int e = blockIdx.x * blockDim.x + threadIdx.x;    // 0 .. 196607
    {
        // L1 weights: W[n(256)][k(768)]
        int n = e / 768, k = e % 768;
        int kc = k >> 6;
        int j  = (k >> 4) & 3;
        int kl = k & 15;
        int p  = kl >> 3;
        int pos = kl & 7;
        int lane = (n & 7) * 4 + (pos >> 1);
        int h = pos & 1;
        int idx = ((((kc * 32 + (n >> 3)) * 4 + j) * 32 + lane) << 2) + p * 2 + h;
        g_B1[0][idx] = __float2half_rn(W1[e]);
        g_B1[1][idx] = __float2half_rn(W3[e]);
    }
    if (e < 128 * 256) {
        // L2 weights: W[n(128)][k(256)]
        int n = e / 256, k = e % 256;
        int j  = k >> 4;
        int kl = k & 15;
        int p  = kl >> 3;
        int pos = kl & 7;
        int lane = (n & 7) * 4 + (pos >> 1);
        int h = pos & 1;
        int idx = ((((n >> 3) * 16 + j) * 32 + lane) << 2) + p * 2 + h;
        g_B2[0][idx] = __float2half_rn(W2[e]);
        g_B2[1][idx] = __float2half_rn(W4[e]);
    }
}

// ----------------------------------------------------------------- main kernel
// MF = number of 16-row m-fragments (4 -> 64-row tile, 2 -> 32-row tile)
template <int MF>
__global__ void __launch_bounds__(256, 2) fused_kernel(
    const float* __restrict__ X, const float* __restrict__ W5,
    float* __restrict__ out, int row_offset) {
    constexpr int ROWS = MF * 16;
    constexpr int AF16_STRIDE = 144;
    constexpr int AF16_BYTES  = ROWS * AF16_STRIDE;
    constexpr int SM_W5   = 0;
    constexpr int SM_PART = 512;
    constexpr int SM_AF16 = 2560;
    constexpr int SM_H1   = SM_AF16 + 2 * AF16_BYTES;
    constexpr int SM_D    = SM_H1 + ROWS * 528;
    constexpr int TPR = 256 / ROWS;        // threads per row for X staging
    constexpr int XF4 = 64 / TPR / 4;      // float4s per thread per chunk (4 or 2)

    extern __shared__ __align__(128) char smem[];
    const uint32_t sb = smem_u32(smem);
    const int tid = threadIdx.x;
    const int w   = tid >> 5;
    const int l   = tid & 31;
    const int lq  = l & 3;

    // global row base of this tile; rows never straddle a batch (4096%32==0)
    const int g0 = row_offset + blockIdx.x * ROWS;
    const float* Xbase = X + (((long long)(g0 >> 12)) * 4097LL + (g0 & 4095) + 1LL) * 2304LL;

    // X prefetch assignment: TPR threads/row, 64/TPR floats each
    const int xrow = tid / TPR, xseg = tid % TPR;
    const float* xsrc_row = Xbase + (long long)xrow * 2304 + xseg * (XF4 * 4);

    float4 xv[XF4];
    auto ldg_chunk = [&](int c) {
        int ss = c / 12, kk = c % 12;
        int soff = (ss == 0) ? 768 : (ss == 1) ? 1536 : 0;   // p1, p2, q
        const float4* src = (const float4*)(xsrc_row + soff + kk * 64);
        #pragma unroll
        for (int i = 0; i < XF4; i++) xv[i] = src[i];
    };
    const uint32_t xdst = sb + SM_AF16 + xrow * AF16_STRIDE + xseg * (XF4 * 8);

    ldg_chunk(0);
    if (tid < 128) ((float*)(smem + SM_W5))[tid] = W5[tid];

    const float* W5s = (const float*)(smem + SM_W5);
    float* parts = (float*)(smem + SM_PART);

    // layer-2 warp grid: 2m x 4n (m-halves of ROWS/2)
    const int wm2 = w >> 2;
    const int wq2 = w & 3;

    const uint32_t aF16lane = sb + SM_AF16 + (l & 15) * AF16_STRIDE + (l >> 4) * 16;
    const uint32_t h1lane   = sb + SM_H1 + (wm2 * (ROWS / 2) + (l & 15)) * 528 + (l >> 4) * 16;

    // distance-2 L1-B ring, preloaded for slice 0 chunk 0 (j0, j1)
    uint2 bv[2][4];
    {
        const uint2* bp = (const uint2*)g_B1[0] + w * 512 + l;
        #pragma unroll
        for (int t = 0; t < 4; t++) {
            bv[0][t] = bp[(t * 4 + 0) * 32];
            bv[1][t] = bp[(t * 4 + 1) * 32];
        }
    }

    int c = 0;
    for (int s = 0; s < 3; s++) {
        const uint2* B1g = (const uint2*)g_B1[s == 2 ? 1 : 0] + w * 512 + l;
        const uint2* B2g = (const uint2*)g_B2[s == 2 ? 1 : 0] + wq2 * 2048 + l;

        // ================= layer 1: acc[MF][4 t][4] = Xslice @ W^T ==============
        float acc[MF][4][4];
        #pragma unroll
        for (int a = 0; a < MF; a++)
            #pragma unroll
            for (int b = 0; b < 4; b++)
                #pragma unroll
                for (int q = 0; q < 4; q++) acc[a][b][q] = 0.f;

        #pragma unroll 1
        for (int kc = 0; kc < 12; kc++) {
            // ---- convert register X -> fp16 AF16[c&1] ----
            {
                uint32_t dst = xdst + (c & 1) * AF16_BYTES;
                #pragma unroll
                for (int i = 0; i < XF4; i += 2) {
                    uint32_t p0 = h2u(__floats2half2_rn(xv[i].x,   xv[i].y));
                    uint32_t p1 = h2u(__floats2half2_rn(xv[i].z,   xv[i].w));
                    uint32_t p2 = h2u(__floats2half2_rn(xv[i+1].x, xv[i+1].y));
                    uint32_t p3 = h2u(__floats2half2_rn(xv[i+1].z, xv[i+1].w));
                    asm volatile("st.shared.v4.b32 [%0], {%1,%2,%3,%4};"
                                 :: "r"(dst + (i / 2) * 16), "r"(p0), "r"(p1), "r"(p2), "r"(p3));
                }
            }
            // LDG for chunk c+1 BEFORE the barrier (WAR-safe; latency overlaps)
            if (c + 1 < 36) ldg_chunk(c + 1);
            __syncthreads();                 // AF16[c&1] complete

            const uint32_t aB = aF16lane + (c & 1) * AF16_BYTES;
            const uint2* bG  = B1g + (c % 12) * 4096;
            const uint2* bGn = bG + 4096;    // next chunk (valid when kc<11)

            #pragma unroll
            for (int j = 0; j < 4; j++) {
                uint32_t afr[MF][4];
                #pragma unroll
                for (int mf = 0; mf < MF; mf++)
                    ldm_x4(afr[mf], aB + mf * 16 * AF16_STRIDE + j * 32);
                #pragma unroll
                for (int t = 0; t < 4; t++) {
                    uint32_t b0 = bv[j & 1][t].x, b1 = bv[j & 1][t].y;
                    if (j < 2)        bv[j & 1][t] = bG[(t * 4 + j + 2) * 32];
                    else if (kc < 11) bv[j & 1][t] = bGn[(t * 4 + (j - 2)) * 32];
                    #pragma unroll
                    for (int mf = 0; mf < MF; mf++)
                        mma16816(acc[mf][t], afr[mf], b0, b1);
                }
            }
            c++;
        }

        // preload layer-2 B j0+j1 EARLY (overlaps the H1 store phase + barrier)
        uint2 bv2[2][4];
        #pragma unroll
        for (int t = 0; t < 4; t++) {
            bv2[0][t] = B2g[(t * 16 + 0) * 32];
            bv2[1][t] = B2g[(t * 16 + 1) * 32];
        }

        // ================= relu -> fp16 -> H1 smem (stride 528) =================
        #pragma unroll
        for (int mf = 0; mf < MF; mf++) {
            #pragma unroll
            for (int t = 0; t < 4; t++) {
                const int r0 = mf * 16 + (l >> 2);
                const int col = w * 32 + t * 8 + lq * 2;
                float* cc = acc[mf][t];
                *(uint32_t*)(smem + SM_H1 + r0 * 528 + col * 2) =
                    h2u(__floats2half2_rn(fmaxf(cc[0], 0.f), fmaxf(cc[1], 0.f)));
                *(uint32_t*)(smem + SM_H1 + (r0 + 8) * 528 + col * 2) =
                    h2u(__floats2half2_rn(fmaxf(cc[2], 0.f), fmaxf(cc[3], 0.f)));
            }
        }
        __syncthreads();

        // ================= layer 2: acc2[MF/2][4 t][4] = H1 @ W2^T ==============
        float acc2[MF / 2][4][4];
        #pragma unroll
        for (int a = 0; a < MF / 2; a++)
            #pragma unroll
            for (int b = 0; b < 4; b++)
                #pragma unroll
                for (int q = 0; q < 4; q++) acc2[a][b][q] = 0.f;

        #pragma unroll
        for (int j = 0; j < 16; j++) {
            uint32_t afr[MF / 2][4];
            #pragma unroll
            for (int mf = 0; mf < MF / 2; mf++)
                ldm_x4(afr[mf], h1lane + mf * 16 * 528 + j * 32);
            #pragma unroll
            for (int t = 0; t < 4; t++) {
                uint32_t b0 = bv2[j & 1][t].x, b1 = bv2[j & 1][t].y;
                if (j < 14) bv2[j & 1][t] = B2g[(t * 16 + j + 2) * 32];
                #pragma unroll
                for (int mf = 0; mf < MF / 2; mf++)
                    mma16816(acc2[mf][t], afr[mf], b0, b1);
            }
        }

        // preload NEXT slice's layer-1 B ring (L2 latency hides under combine)
        if (s < 2) {
            const uint2* bn = (const uint2*)g_B1[s == 1 ? 1 : 0] + w * 512 + l;
            #pragma unroll
            for (int t = 0; t < 4; t++) {
                bv[0][t] = bn[(t * 4 + 0) * 32];
                bv[1][t] = bn[(t * 4 + 1) * 32];
            }
        }

        // D cells: warp (wm2,wq2) owns rows [wm2*ROWS/2,+ROWS/2) x cols
        // [wq2*32,+32) in ALL slices -> warp-private, no race.

        // ================= combine via D buffer (stride 272) ====================
        if (s == 0) {
            #pragma unroll
            for (int mf = 0; mf < MF / 2; mf++)
                #pragma unroll
                for (int t = 0; t < 4; t++) {
                    const int r0 = wm2 * (ROWS / 2) + mf * 16 + (l >> 2);
                    const int col = wq2 * 32 + t * 8 + lq * 2;
                    float* cc = acc2[mf][t];
                    *(uint32_t*)(smem + SM_D + r0 * 272 + col * 2) =
                        h2u(__floats2half2_rn(fmaxf(cc[0], 0.f), fmaxf(cc[1], 0.f)));
                    *(uint32_t*)(smem + SM_D + (r0 + 8) * 272 + col * 2) =
                        h2u(__floats2half2_rn(fmaxf(cc[2], 0.f), fmaxf(cc[3], 0.f)));
                }
        } else if (s == 1) {
            #pragma unroll
            for (int mf = 0; mf < MF / 2; mf++)
                #pragma unroll
                for (int t = 0; t < 4; t++) {
                    const int r0 = wm2 * (ROWS / 2) + mf * 16 + (l >> 2);
                    const int col = wq2 * 32 + t * 8 + lq * 2;
                    float* cc = acc2[mf][t];
                    uint32_t* d0 = (uint32_t*)(smem + SM_D + r0 * 272 + col * 2);
                    uint32_t* d1 = (uint32_t*)(smem + SM_D + (r0 + 8) * 272 + col * 2);
                    float2 fa = __half22float2(*(__half2*)d0);
                    float2 fb = __half22float2(*(__half2*)d1);
                    *d0 = h2u(__floats2half2_rn(fabsf(fa.x - fmaxf(cc[0], 0.f)),
                                                fabsf(fa.y - fmaxf(cc[1], 0.f))));
                    *d1 = h2u(__floats2half2_rn(fabsf(fb.x - fmaxf(cc[2], 0.f)),
                                                fabsf(fb.y - fmaxf(cc[3], 0.f))));
                }
        } else {
            float pd[MF / 2][2];
            #pragma unroll
            for (int mf = 0; mf < MF / 2; mf++) { pd[mf][0] = 0.f; pd[mf][1] = 0.f; }
            #pragma unroll
            for (int mf = 0; mf < MF / 2; mf++)
                #pragma unroll
                for (int t = 0; t < 4; t++) {
                    const int r0 = wm2 * (ROWS / 2) + mf * 16 + (l >> 2);
                    const int col = wq2 * 32 + t * 8 + lq * 2;
                    float* cc = acc2[mf][t];
                    float2 da = __half22float2(*(__half2*)(smem + SM_D + r0 * 272 + col * 2));
                    float2 db = __half22float2(*(__half2*)(smem + SM_D + (r0 + 8) * 272 + col * 2));
                    float w0 = W5s[col], w1 = W5s[col + 1];
                    pd[mf][0] += w0 * fmaxf(cc[0], 0.f) * da.x + w1 * fmaxf(cc[1], 0.f) * da.y;
                    pd[mf][1] += w0 * fmaxf(cc[2], 0.f) * db.x + w1 * fmaxf(cc[3], 0.f) * db.y;
                }
            #pragma unroll
            for (int mf = 0; mf < MF / 2; mf++)
                #pragma unroll
                for (int rr = 0; rr < 2; rr++) {
                    float v = pd[mf][rr];
                    v += __shfl_xor_sync(0xFFFFFFFF, v, 1);
                    v += __shfl_xor_sync(0xFFFFFFFF, v, 2);
                    if (lq == 0) {
                        int row = wm2 * (ROWS / 2) + mf * 16 + rr * 8 + (l >> 2);
                        parts[row * 4 + wq2] = v;
                    }
                }
        }
    }

    __syncthreads();
    if (tid < ROWS) {
        const float* p = parts + tid * 4;
        float sum = (p[0] + p[1]) + (p[2] + p[3]);
        out[g0 + tid] = tanhf(fmaxf(sum, 0.f));
    }
}

// smem sizes per instantiation
static constexpr int SMEM_MF4 = 2560 + 2 * (64 * 144) + 64 * 528 + 64 * 272;  // 72192
static constexpr int SMEM_MF2 = 2560 + 2 * (32 * 144) + 32 * 528 + 32 * 272;  // 37376

// ------------------------------------------------------------------- launcher
extern "C" void kernel_launch(void* const* d_in, const int* in_sizes, int n_in,
                              void* d_out, int out_size) {
    const float* X  = (const float*)d_in[0];
    const float* W1 = (const float*)d_in[1];
    const float* W2 = (const float*)d_in[2];
    const float* W3 = (const float*)d_in[3];
    const float* W4 = (const float*)d_in[4];
    const float* W5 = (const float*)d_in[5];
    (void)in_sizes; (void)n_in; (void)out_size;

    cudaFuncSetAttribute(fused_kernel<4>, cudaFuncAttributeMaxDynamicSharedMemorySize, SMEM_MF4);
    cudaFuncSetAttribute(fused_kernel<2>, cudaFuncAttributeMaxDynamicSharedMemorySize, SMEM_MF2);

    prep_kernel<<<768, 256>>>(W1, W2, W3, W4);
    // 888 x 64-row tiles = rows [0, 56832): exactly 3 full waves at 2 CTA/SM
    fused_kernel<4><<<888, 256, SMEM_MF4>>>(X, W5, (float*)d_out, 0);
    // 272 x 32-row tiles = rows [56832, 65536): one ~0.55-wave remainder pass
    fused_kernel<2><<<272, 256, SMEM_MF2>>>(X, W5, (float*)d_out, 56832);
}

// round 16
// speedup vs baseline: 1.8599x; 1.0330x over previous
#include <cuda_runtime.h>
#include <cuda_fp16.h>
#include <cstdint>

// ============================================================================
// CATSCluster fused kernel — sm_103 baseline-PTX tensor path.
// Round-16: restore r11 (285.3us, the measured optimum of this family) with
// one zero-risk tweak: X loads are STREAMING (ld.global.nc, evict-first) —
// X is read exactly once (604MB) while weights are L2-resident and re-read by
// all 2048 CTAs, so X should not displace them.
//
// Proven config: 64-row block, 256 thr, 2 CTAs/SM, L1 warp tile 64m x 32n,
// L2 warp tile 32m x 32n (2m x 4n grid), register-X prefetch issued before
// the single per-chunk barrier, distance-2 B-fragment rings in both GEMMs,
// ldmatrix A/H1 feed, fragment-packed weights ([n8][j][lane], 256B-coalesced).
//
//   X = X_data[:, 1:, :]  (16 x 4096 x 2304 fp32)
//   p1 = X[.., 768:1536] -> relu(relu(p1@W1^T)@W2^T) = Ha2   (128)
//   p2 = X[..,1536:2304] -> same weights             = Hb2
//   q  = X[..,   0: 768] -> relu(relu(q @W3^T)@W4^T) = Hq2
//   out = tanh(relu( (Hq2 * |Ha2-Hb2|) @ W5^T ))
// ============================================================================

// ---- smem layout (bytes), 64-row block ----
static constexpr int AF16_STRIDE = 144;                   // 64 f16 + 16B pad
static constexpr int AF16_BYTES  = 64 * AF16_STRIDE;      // 9216
static constexpr int SM_W5   = 0;                         // 512 B
static constexpr int SM_PART = 512;                       // float[64][4] = 1024
static constexpr int SM_AF16 = 2560;                      // 2 x 9216 (double buffer)
static constexpr int SM_H1   = SM_AF16 + 2 * AF16_BYTES;  // 64 x 528 = 33792
static constexpr int SM_D    = SM_H1 + 64 * 528;          // 64 x 272 = 17408
static constexpr int SMEM_BYTES = SM_D + 64 * 272;        // 74368 -> 2 CTAs/SM

// Fragment-packed fp16 weights (prep kernel fills these every launch).
// L1: [chunk 12][n8-tile 32][k16 4][lane 32][4 halves]
// L2: [n8-tile 16][k16 16][lane 32][4 halves]
__device__ __half g_B1[2][12 * 32 * 4 * 32 * 4];   // W1, W3
__device__ __half g_B2[2][16 * 16 * 32 * 4];       // W2, W4

// ---------------------------------------------------------------- helpers
__device__ __forceinline__ uint32_t smem_u32(const void* p) {
    return (uint32_t)__cvta_generic_to_shared(p);
}
__device__ __forceinline__ void ldm_x4(uint32_t r[4], uint32_t addr) {
    asm volatile("ldmatrix.sync.aligned.m8n8.x4.shared.b16 {%0,%1,%2,%3}, [%4];"
                 : "=r"(r[0]), "=r"(r[1]), "=r"(r[2]), "=r"(r[3]) : "r"(addr));
}
__device__ __forceinline__ void mma16816(float c[4], const uint32_t a[4],
                                         uint32_t b0, uint32_t b1) {
    asm volatile(
        "mma.sync.aligned.m16n8k16.row.col.f32.f16.f16.f32 "
        "{%0,%1,%2,%3}, {%4,%5,%6,%7}, {%8,%9}, {%0,%1,%2,%3};"
        : "+f"(c[0]), "+f"(c[1]), "+f"(c[2]), "+f"(c[3])
        : "r"(a[0]), "r"(a[1]), "r"(a[2]), "r"(a[3]), "r"(b0), "r"(b1));
}
__device__ __forceinline__ uint32_t h2u(__half2 h) {
    return *reinterpret_cast<uint32_t*>(&h);
}
// streaming float4 load (read-once data: L1 ok, L2 evict-first)
__device__ __forceinline__ float4 ldg_stream(const float4* p) {
    float4 v;
    asm volatile("ld.global.nc.L1::evict_first.v4.f32 {%0,%1,%2,%3}, [%4];"
                 : "=f"(v.x), "=f"(v.y), "=f"(v.z), "=f"(v.w) : "l"(p));
    return v;
}

// ------------------------------------------------- weight frag-pack kernel
__global__ void prep_kernel(const float* __restrict__ W1, const float* __restrict__ W2,
                            const float* __restrict__ W3, const float* __restrict__ W4) {
    int e = blockIdx.x * blockDim.x + threadIdx.x;    // 0 .. 196607
    {
        // L1 weights: W[n(256)][k(768)]
        int n = e / 768, k = e % 768;
        int kc = k >> 6;
        int j  = (k >> 4) & 3;
        int kl = k & 15;
        int p  = kl >> 3;
        int pos = kl & 7;
        int lane = (n & 7) * 4 + (pos >> 1);
        int h = pos & 1;
        int idx = ((((kc * 32 + (n >> 3)) * 4 + j) * 32 + lane) << 2) + p * 2 + h;
        g_B1[0][idx] = __float2half_rn(W1[e]);
        g_B1[1][idx] = __float2half_rn(W3[e]);
    }
    if (e < 128 * 256) {
        // L2 weights: W[n(128)][k(256)]
        int n = e / 256, k = e % 256;
        int j  = k >> 4;
        int kl = k & 15;
        int p  = kl >> 3;
        int pos = kl & 7;
        int lane = (n & 7) * 4 + (pos >> 1);
        int h = pos & 1;
        int idx = ((((n >> 3) * 16 + j) * 32 + lane) << 2) + p * 2 + h;
        g_B2[0][idx] = __float2half_rn(W2[e]);
        g_B2[1][idx] = __float2half_rn(W4[e]);
    }
}

// ----------------------------------------------------------------- main kernel
__global__ void __launch_bounds__(256, 2) fused_kernel(
    const float* __restrict__ X, const float* __restrict__ W5, float* __restrict__ out) {
    extern __shared__ __align__(128) char smem[];
    const uint32_t sb = smem_u32(smem);
    const int tid = threadIdx.x;
    const int w   = tid >> 5;           // warp 0..7
    const int l   = tid & 31;
    const int lq  = l & 3;

    const long long blk = blockIdx.x;                  // 1024 blocks, 64 rows each
    const float* Xbase = X + ((blk >> 6) * 4097LL + (blk & 63) * 64LL + 1LL) * 2304LL;

    // X prefetch assignment: 4 threads/row, 16 floats (64B) each
    const int xrow = tid >> 2, xseg = tid & 3;
    const float* xsrc_row = Xbase + (long long)xrow * 2304 + xseg * 16;

    // chunk c (0..35): slice s=c/12, k-chunk kc=c%12, AF16 buffer c&1.
    float4 xv0, xv1, xv2, xv3;
    auto ldg_chunk = [&](int c) {
        int ss = c / 12, kk = c % 12;
        int soff = (ss == 0) ? 768 : (ss == 1) ? 1536 : 0;   // p1, p2, q
        const float4* src = (const float4*)(xsrc_row + soff + kk * 64);
        xv0 = ldg_stream(src + 0);
        xv1 = ldg_stream(src + 1);
        xv2 = ldg_stream(src + 2);
        xv3 = ldg_stream(src + 3);
    };
    // this thread's STS target within an AF16 buffer (32B fp16 for its 16 floats)
    const uint32_t xdst = sb + SM_AF16 + xrow * AF16_STRIDE + xseg * 32;

    ldg_chunk(0);
    if (tid < 128) ((float*)(smem + SM_W5))[tid] = W5[tid];

    const float* W5s = (const float*)(smem + SM_W5);
    float* parts = (float*)(smem + SM_PART);

    // layer-2 warp grid: 2m x 4n
    const int wm2 = w >> 2;             // m-half (32 rows)
    const int wq2 = w & 3;              // n-quarter (32 cols)

    // ldmatrix lane addressing
    const uint32_t aF16lane = sb + SM_AF16 + (l & 15) * AF16_STRIDE + (l >> 4) * 16;
    const uint32_t h1lane   = sb + SM_H1 + (wm2 * 32 + (l & 15)) * 528 + (l >> 4) * 16;

    // distance-2 L1-B ring, preloaded for slice 0 chunk 0 (j0, j1)
    uint2 bv[2][4];
    {
        const uint2* bp = (const uint2*)g_B1[0] + w * 512 + l;
        #pragma unroll
        for (int t = 0; t < 4; t++) {
            bv[0][t] = bp[(t * 4 + 0) * 32];
            bv[1][t] = bp[(t * 4 + 1) * 32];
        }
    }

    int c = 0;
    for (int s = 0; s < 3; s++) {
        const uint2* B1g = (const uint2*)g_B1[s == 2 ? 1 : 0] + w * 512 + l;
        const uint2* B2g = (const uint2*)g_B2[s == 2 ? 1 : 0] + wq2 * 2048 + l;

        // ================= layer 1: acc[4 mf][4 t][4] = Xslice @ W^T ============
        float acc[4][4][4];
        #pragma unroll
        for (int a = 0; a < 4; a++)
            #pragma unroll
            for (int b = 0; b < 4; b++)
                #pragma unroll
                for (int q = 0; q < 4; q++) acc[a][b][q] = 0.f;

        #pragma unroll 1
        for (int kc = 0; kc < 12; kc++) {
            // ---- convert register X -> fp16 AF16[c&1] (32B STS) ----
            {
                uint32_t dst = xdst + (c & 1) * AF16_BYTES;
                uint32_t p0 = h2u(__floats2half2_rn(xv0.x, xv0.y));
                uint32_t p1 = h2u(__floats2half2_rn(xv0.z, xv0.w));
                uint32_t p2 = h2u(__floats2half2_rn(xv1.x, xv1.y));
                uint32_t p3 = h2u(__floats2half2_rn(xv1.z, xv1.w));
                asm volatile("st.shared.v4.b32 [%0], {%1,%2,%3,%4};"
                             :: "r"(dst), "r"(p0), "r"(p1), "r"(p2), "r"(p3));
                uint32_t p4 = h2u(__floats2half2_rn(xv2.x, xv2.y));
                uint32_t p5 = h2u(__floats2half2_rn(xv2.z, xv2.w));
                uint32_t p6 = h2u(__floats2half2_rn(xv3.x, xv3.y));
                uint32_t p7 = h2u(__floats2half2_rn(xv3.z, xv3.w));
                asm volatile("st.shared.v4.b32 [%0], {%1,%2,%3,%4};"
                             :: "r"(dst + 16), "r"(p4), "r"(p5), "r"(p6), "r"(p7));
            }
            // LDG for chunk c+1 issued BEFORE the barrier (WAR-safe: STS above
            // consumed xv); global latency overlaps barrier + this chunk's MMAs.
            if (c + 1 < 36) ldg_chunk(c + 1);
            __syncthreads();                 // AF16[c&1] complete (barrier c-1 ordered
                                             // all MMA readers of this buffer)

            const uint32_t aB = aF16lane + (c & 1) * AF16_BYTES;
            const uint2* bG  = B1g + (c % 12) * 4096;
            const uint2* bGn = bG + 4096;    // next chunk (valid when kc<11)

            #pragma unroll
            for (int j = 0; j < 4; j++) {
                uint32_t afr[4][4];
                #pragma unroll
                for (int mf = 0; mf < 4; mf++)
                    ldm_x4(afr[mf], aB + mf * 16 * AF16_STRIDE + j * 32);
                #pragma unroll
                for (int t = 0; t < 4; t++) {
                    uint32_t b0 = bv[j & 1][t].x, b1 = bv[j & 1][t].y;
                    // refill this ring slot at distance 2
                    if (j < 2)        bv[j & 1][t] = bG[(t * 4 + j + 2) * 32];
                    else if (kc < 11) bv[j & 1][t] = bGn[(t * 4 + (j - 2)) * 32];
                    mma16816(acc[0][t], afr[0], b0, b1);
                    mma16816(acc[1][t], afr[1], b0, b1);
                    mma16816(acc[2][t], afr[2], b0, b1);
                    mma16816(acc[3][t], afr[3], b0, b1);
                }
            }
            c++;
        }

        // preload layer-2 B j0+j1 EARLY (their L2 latency overlaps the whole
        // H1 store phase + barrier)
        uint2 bv2[2][4];
        #pragma unroll
        for (int t = 0; t < 4; t++) {
            bv2[0][t] = B2g[(t * 16 + 0) * 32];
            bv2[1][t] = B2g[(t * 16 + 1) * 32];
        }

        // ================= relu -> fp16 -> H1 smem (stride 528) =================
        #pragma unroll
        for (int mf = 0; mf < 4; mf++) {
            #pragma unroll
            for (int t = 0; t < 4; t++) {
                const int r0 = mf * 16 + (l >> 2);
                const int col = w * 32 + t * 8 + lq * 2;
                float* cc = acc[mf][t];
                *(uint32_t*)(smem + SM_H1 + r0 * 528 + col * 2) =
                    h2u(__floats2half2_rn(fmaxf(cc[0], 0.f), fmaxf(cc[1], 0.f)));
                *(uint32_t*)(smem + SM_H1 + (r0 + 8) * 528 + col * 2) =
                    h2u(__floats2half2_rn(fmaxf(cc[2], 0.f), fmaxf(cc[3], 0.f)));
            }
        }
        __syncthreads();

        // ================= layer 2: acc2[2 mf][4 t][4] = H1 @ W2^T ==============
        // warp tile 32m x 32n (grid 2m x 4n)
        float acc2[2][4][4];
        #pragma unroll
        for (int a = 0; a < 2; a++)
            #pragma unroll
            for (int b = 0; b < 4; b++)
                #pragma unroll
                for (int q = 0; q < 4; q++) acc2[a][b][q] = 0.f;

        #pragma unroll
        for (int j = 0; j < 16; j++) {
            uint32_t afr[2][4];
            #pragma unroll
            for (int mf = 0; mf < 2; mf++)
                ldm_x4(afr[mf], h1lane + mf * 16 * 528 + j * 32);
            #pragma unroll
            for (int t = 0; t < 4; t++) {
                uint32_t b0 = bv2[j & 1][t].x, b1 = bv2[j & 1][t].y;
                if (j < 14) bv2[j & 1][t] = B2g[(t * 16 + j + 2) * 32];
                mma16816(acc2[0][t], afr[0], b0, b1);
                mma16816(acc2[1][t], afr[1], b0, b1);
            }
        }

        // preload NEXT slice's layer-1 B ring before the combine phase so its
        // L2 latency hides under the combine ALU work (s==2 has no next slice)
        if (s < 2) {
            const uint2* bn = (const uint2*)g_B1[s == 1 ? 1 : 0] + w * 512 + l;
            #pragma unroll
            for (int t = 0; t < 4; t++) {
                bv[0][t] = bn[(t * 4 + 0) * 32];
                bv[1][t] = bn[(t * 4 + 1) * 32];
            }
        }

        // D-buffer cells below: warp (wm2,wq2) owns rows [wm2*32,+32) x cols
        // [wq2*32,+32) in ALL slices -> no cross-warp race; H1 rewritten only
        // after the next slice's chunk barriers.

        // ================= combine via D buffer (stride 272) ====================
        if (s == 0) {
            #pragma unroll
            for (int mf = 0; mf < 2; mf++)
                #pragma unroll
                for (int t = 0; t < 4; t++) {
                    const int r0 = wm2 * 32 + mf * 16 + (l >> 2);
                    const int col = wq2 * 32 + t * 8 + lq * 2;
                    float* cc = acc2[mf][t];
                    *(uint32_t*)(smem + SM_D + r0 * 272 + col * 2) =
                        h2u(__floats2half2_rn(fmaxf(cc[0], 0.f), fmaxf(cc[1], 0.f)));
                    *(uint32_t*)(smem + SM_D + (r0 + 8) * 272 + col * 2) =
                        h2u(__floats2half2_rn(fmaxf(cc[2], 0.f), fmaxf(cc[3], 0.f)));
                }
        } else if (s == 1) {
            #pragma unroll
            for (int mf = 0; mf < 2; mf++)
                #pragma unroll
                for (int t = 0; t < 4; t++) {
                    const int r0 = wm2 * 32 + mf * 16 + (l >> 2);
                    const int col = wq2 * 32 + t * 8 + lq * 2;
                    float* cc = acc2[mf][t];
                    uint32_t* d0 = (uint32_t*)(smem + SM_D + r0 * 272 + col * 2);
                    uint32_t* d1 = (uint32_t*)(smem + SM_D + (r0 + 8) * 272 + col * 2);
                    float2 fa = __half22float2(*(__half2*)d0);
                    float2 fb = __half22float2(*(__half2*)d1);
                    *d0 = h2u(__floats2half2_rn(fabsf(fa.x - fmaxf(cc[0], 0.f)),
                                                fabsf(fa.y - fmaxf(cc[1], 0.f))));
                    *d1 = h2u(__floats2half2_rn(fabsf(fb.x - fmaxf(cc[2], 0.f)),
                                                fabsf(fb.y - fmaxf(cc[3], 0.f))));
                }
        } else {
            // s==2: pd[mf][rr] = per-row partial over this warp's 32 cols
            float pd[2][2] = {{0.f, 0.f}, {0.f, 0.f}};
            #pragma unroll
            for (int mf = 0; mf < 2; mf++)
                #pragma unroll
                for (int t = 0; t < 4; t++) {
                    const int r0 = wm2 * 32 + mf * 16 + (l >> 2);
                    const int col = wq2 * 32 + t * 8 + lq * 2;
                    float* cc = acc2[mf][t];
                    float2 da = __half22float2(*(__half2*)(smem + SM_D + r0 * 272 + col * 2));
                    float2 db = __half22float2(*(__half2*)(smem + SM_D + (r0 + 8) * 272 + col * 2));
                    float w0 = W5s[col], w1 = W5s[col + 1];
                    pd[mf][0] += w0 * fmaxf(cc[0], 0.f) * da.x + w1 * fmaxf(cc[1], 0.f) * da.y;
                    pd[mf][1] += w0 * fmaxf(cc[2], 0.f) * db.x + w1 * fmaxf(cc[3], 0.f) * db.y;
                }
            #pragma unroll
            for (int mf = 0; mf < 2; mf++)
                #pragma unroll
                for (int rr = 0; rr < 2; rr++) {
                    float v = pd[mf][rr];
                    v += __shfl_xor_sync(0xFFFFFFFF, v, 1);
                    v += __shfl_xor_sync(0xFFFFFFFF, v, 2);
                    if (lq == 0) {
                        int row = wm2 * 32 + mf * 16 + rr * 8 + (l >> 2);
                        parts[row * 4 + wq2] = v;    // warp's 32-col partial
                    }
                }
        }
    }

    __syncthreads();
    if (tid < 64) {
        const float* p = parts + tid * 4;
        float sum = (p[0] + p[1]) + (p[2] + p[3]);
        out[blk * 64 + tid] = tanhf(fmaxf(sum, 0.f));
    }
}

// ------------------------------------------------------------------- launcher
extern "C" void kernel_launch(void* const* d_in, const int* in_sizes, int n_in,
                              void* d_out, int out_size) {
    const float* X  = (const float*)d_in[0];
    const float* W1 = (const float*)d_in[1];
    const float* W2 = (const float*)d_in[2];
    const float* W3 = (const float*)d_in[3];
    const float* W4 = (const float*)d_in[4];
    const float* W5 = (const float*)d_in[5];
    (void)in_sizes; (void)n_in; (void)out_size;

    cudaFuncSetAttribute(fused_kernel, cudaFuncAttributeMaxDynamicSharedMemorySize, SMEM_BYTES);

    prep_kernel<<<768, 256>>>(W1, W2, W3, W4);
    fused_kernel<<<1024, 256, SMEM_BYTES>>>(X, W5, (float*)d_out);
}